// round 3
// baseline (speedup 1.0000x reference)
#include <cuda_runtime.h>
#include <math.h>

#define N_NODES 50000
#define N_EDGES 800000
#define F 64
#define KW 129   // 2*F + 1

// ---------------- scratch (static device globals; no runtime alloc) --------
__device__ int   g_deg[N_NODES];
__device__ int   g_cursor[N_NODES];
__device__ int   g_row_ptr[N_NODES + 1];
__device__ int   g_csr_src[N_EDGES];
__device__ float g_he[N_NODES];
__device__ float g_h0[(size_t)N_NODES * F];
__device__ float g_h1[(size_t)N_NODES * F];
__device__ float g_aggr[(size_t)N_NODES * F];

// ---------------- preprocessing ---------------------------------------------
__global__ void k_zero() {
    int i = blockIdx.x * blockDim.x + threadIdx.x;
    if (i < N_NODES) { g_deg[i] = 0; g_cursor[i] = 0; g_he[i] = 0.f; }
}

__global__ void k_hist(const int* __restrict__ dst, const float* __restrict__ ef) {
    int e = blockIdx.x * blockDim.x + threadIdx.x;
    if (e < N_EDGES) {
        int d = dst[e];
        atomicAdd(&g_deg[d], 1);
        atomicAdd(&g_he[d], ef[e]);
    }
}

// single-block exclusive scan over g_deg -> g_row_ptr (50k elements, ~49 chunks)
__global__ void k_scan() {
    __shared__ int s[1024];
    __shared__ int carry_s;
    int tid = threadIdx.x;
    if (tid == 0) { carry_s = 0; g_row_ptr[0] = 0; }
    __syncthreads();
    const int nchunks = (N_NODES + 1023) / 1024;
    for (int c = 0; c < nchunks; c++) {
        int i = c * 1024 + tid;
        int v = (i < N_NODES) ? g_deg[i] : 0;
        s[tid] = v;
        __syncthreads();
        // Hillis-Steele inclusive scan
        for (int off = 1; off < 1024; off <<= 1) {
            int t = (tid >= off) ? s[tid - off] : 0;
            __syncthreads();
            s[tid] += t;
            __syncthreads();
        }
        int carry = carry_s;
        if (i < N_NODES) g_row_ptr[i + 1] = s[tid] + carry;
        __syncthreads();
        if (tid == 0) carry_s = carry + s[1023];
        __syncthreads();
    }
}

__global__ void k_scatter(const int* __restrict__ src, const int* __restrict__ dst) {
    int e = blockIdx.x * blockDim.x + threadIdx.x;
    if (e < N_EDGES) {
        int d = dst[e];
        int pos = g_row_ptr[d] + atomicAdd(&g_cursor[d], 1);
        g_csr_src[pos] = src[e];
    }
}

// ---------------- neighbor aggregation (one warp per node, CSR gather) ------
__global__ void k_aggr(const float* __restrict__ h) {
    int wid  = (blockIdx.x * blockDim.x + threadIdx.x) >> 5;
    int lane = threadIdx.x & 31;
    if (wid >= N_NODES) return;
    int beg = g_row_ptr[wid];
    int end = g_row_ptr[wid + 1];
    float ax = 0.f, ay = 0.f;
    for (int e = beg; e < end; e++) {
        int s = g_csr_src[e];
        float2 v = *(const float2*)(h + (size_t)s * F + lane * 2);
        ax += v.x; ay += v.y;
    }
    float2 o; o.x = ax; o.y = ay;
    *(float2*)(g_aggr + (size_t)wid * F + lane * 2) = o;
}

// ---------------- fused linear layer: out = act(h@Wa^T + aggr@Wb^T + he*wc + b)
// tile: 64 nodes x 64 outputs, 256 threads, 4x4 register micro-tile.
// act: 0=none, 1=relu, 2=sigmoid
__global__ void k_layer(const float* __restrict__ h,
                        const float* __restrict__ W,   // [64][129] row-major
                        const float* __restrict__ b,   // [64]
                        float* __restrict__ out, int act) {
    __shared__ float tile[64][68];   // transposed: tile[k][node], padded stride
    __shared__ float Wt[64][64];     // transposed: Wt[k][out]
    int tid = threadIdx.x;
    int tc = tid & 15;        // output group 0..15  (4 outputs each)
    int tr = tid >> 4;        // node   group 0..15  (4 nodes each)
    int base = blockIdx.x * 64;

    float acc[4][4];
#pragma unroll
    for (int i = 0; i < 4; i++)
#pragma unroll
        for (int j = 0; j < 4; j++) acc[i][j] = 0.f;

    for (int phase = 0; phase < 2; phase++) {
        const float* hp = phase ? g_aggr : h;
        __syncthreads();   // protect smem from previous phase's readers
        // stage input tile (transposed)
        for (int i = tid; i < 4096; i += 256) {
            int nn = i >> 6, k = i & 63;
            int node = base + nn;
            tile[k][nn] = (node < N_NODES) ? hp[(size_t)node * F + k] : 0.f;
        }
        // stage weight half (transposed)
        for (int i = tid; i < 4096; i += 256) {
            int j = i >> 6, k = i & 63;
            Wt[k][j] = W[j * KW + phase * 64 + k];
        }
        __syncthreads();
#pragma unroll 8
        for (int k = 0; k < 64; k++) {
            float4 a = *(const float4*)&tile[k][tr * 4];
            float4 w = *(const float4*)&Wt[k][tc * 4];
            float av[4] = {a.x, a.y, a.z, a.w};
            float wv[4] = {w.x, w.y, w.z, w.w};
#pragma unroll
            for (int i = 0; i < 4; i++)
#pragma unroll
                for (int j = 0; j < 4; j++) acc[i][j] += av[i] * wv[j];
        }
    }

    // epilogue: rank-1 edge term + bias + activation
#pragma unroll
    for (int i = 0; i < 4; i++) {
        int node = base + tr * 4 + i;
        if (node >= N_NODES) break;
        float hev = g_he[node];
        float4 o;
        float* op = &o.x;
#pragma unroll
        for (int j = 0; j < 4; j++) {
            int c = tc * 4 + j;
            float v = acc[i][j] + hev * W[c * KW + 128] + b[c];
            if (act == 1)      v = fmaxf(v, 0.f);
            else if (act == 2) v = 1.f / (1.f + expf(-v));
            op[j] = v;
        }
        *(float4*)(out + (size_t)node * F + tc * 4) = o;
    }
}

// ---------------- final layer: 2 outputs per node (warp per node) -----------
__global__ void k_final(const float* __restrict__ h,
                        const float* __restrict__ W2,  // [2][129]
                        const float* __restrict__ b2,  // [2]
                        float* __restrict__ out) {
    int wid  = (blockIdx.x * blockDim.x + threadIdx.x) >> 5;
    int lane = threadIdx.x & 31;
    if (wid >= N_NODES) return;
    float2 hv = *(const float2*)(h      + (size_t)wid * F + lane * 2);
    float2 av = *(const float2*)(g_aggr + (size_t)wid * F + lane * 2);
    float he = g_he[wid];
#pragma unroll
    for (int c = 0; c < 2; c++) {
        const float* w = W2 + c * KW;
        float p = hv.x * w[2 * lane] + hv.y * w[2 * lane + 1]
                + av.x * w[64 + 2 * lane] + av.y * w[64 + 2 * lane + 1];
#pragma unroll
        for (int off = 16; off; off >>= 1) p += __shfl_xor_sync(0xffffffffu, p, off);
        if (lane == 0) out[wid * 2 + c] = p + he * w[128] + b2[c];
    }
}

// ---------------- launch -----------------------------------------------------
extern "C" void kernel_launch(void* const* d_in, const int* in_sizes, int n_in,
                              void* d_out, int out_size) {
    const float* node_feat = (const float*)d_in[0];
    const float* edge_feat = (const float*)d_in[1];
    const int*   src       = (const int*)  d_in[2];
    const int*   dst       = (const int*)  d_in[3];
    const float* W1        = (const float*)d_in[4];
    const float* b1        = (const float*)d_in[5];
    const float* Wmid      = (const float*)d_in[6];
    const float* bmid      = (const float*)d_in[7];
    const float* W2        = (const float*)d_in[8];
    const float* b2        = (const float*)d_in[9];
    float* out = (float*)d_out;

    void *p0, *p1;
    cudaGetSymbolAddress(&p0, g_h0);
    cudaGetSymbolAddress(&p1, g_h1);
    float* h0 = (float*)p0;
    float* h1 = (float*)p1;

    // preprocessing: CSR build + constant edge aggregation
    k_zero<<<(N_NODES + 255) / 256, 256>>>();
    k_hist<<<(N_EDGES + 255) / 256, 256>>>(dst, edge_feat);
    k_scan<<<1, 1024>>>();
    k_scatter<<<(N_EDGES + 255) / 256, 256>>>(src, dst);

    const int aggr_blocks  = (N_NODES * 32 + 255) / 256;
    const int layer_blocks = (N_NODES + 63) / 64;

    // layer 1: node_feat -> h0 (relu)
    k_aggr<<<aggr_blocks, 256>>>(node_feat);
    k_layer<<<layer_blocks, 256>>>(node_feat, W1, b1, h0, 1);

    // 5 mid layers (relu x4, sigmoid last), ping-pong h0/h1
    const float* cur = h0;
    float* nxt = h1;
    for (int i = 0; i < 5; i++) {
        k_aggr<<<aggr_blocks, 256>>>(cur);
        k_layer<<<layer_blocks, 256>>>(cur, Wmid + (size_t)i * F * KW,
                                       bmid + (size_t)i * F, nxt, (i < 4) ? 1 : 2);
        float* t = (float*)cur; cur = nxt; nxt = t;
    }

    // final layer: 2 logits per node -> d_out
    k_aggr<<<aggr_blocks, 256>>>(cur);
    k_final<<<aggr_blocks, 256>>>(cur, W2, b2, out);
}

// round 6
// speedup vs baseline: 1.1511x; 1.1511x over previous
#include <cuda_runtime.h>
#include <math.h>

#define N_NODES 50000
#define N_EDGES 800000
#define F 64
#define KW 129           // 2*F + 1
#define NPART ((N_NODES + 255) / 256)   // 196
#define TILE_PAD 132     // 128 nodes + 4 pad (keeps 16B alignment, breaks bank conflicts)
#define SMEM_BYTES ((64 * TILE_PAD + 64 * 64) * 4)   // 50176

// ---------------- scratch (static device globals) ---------------------------
__device__ int   g_deg[N_NODES];
__device__ int   g_cursor[N_NODES];
__device__ int   g_row_ptr[N_NODES + 1];
__device__ int   g_csr_src[N_EDGES];
__device__ int   g_part[NPART];
__device__ float g_he[N_NODES];
__device__ float g_h0[(size_t)N_NODES * F];
__device__ float g_h1[(size_t)N_NODES * F];

// ---------------- f32x2 helpers ---------------------------------------------
#define FMA2(d, a, b) \
    asm("fma.rn.f32x2 %0, %1, %2, %0;" : "+l"(d) : "l"(a), "l"(b))
#define PACK_DUP(out, f) \
    asm("mov.b64 %0, {%1, %1};" : "=l"(out) : "f"(f))

// ---------------- preprocessing ---------------------------------------------
__global__ void k_zero() {
    int i = blockIdx.x * blockDim.x + threadIdx.x;
    if (i < N_NODES) { g_deg[i] = 0; g_cursor[i] = 0; g_he[i] = 0.f; }
}

__global__ void k_hist(const int* __restrict__ dst, const float* __restrict__ ef) {
    int e = blockIdx.x * blockDim.x + threadIdx.x;
    if (e < N_EDGES) {
        int d = dst[e];
        atomicAdd(&g_deg[d], 1);
        atomicAdd(&g_he[d], ef[e]);
    }
}

// block-level inclusive scan of one int per thread (256 threads)
__device__ __forceinline__ int block_scan_inc(int v, int* ws) {
    int lane = threadIdx.x & 31, warp = threadIdx.x >> 5;
    int x = v;
#pragma unroll
    for (int off = 1; off < 32; off <<= 1) {
        int t = __shfl_up_sync(0xffffffffu, x, off);
        if (lane >= off) x += t;
    }
    if (lane == 31) ws[warp] = x;
    __syncthreads();
    if (warp == 0 && lane < 8) {
        int y = ws[lane];
#pragma unroll
        for (int off = 1; off < 8; off <<= 1) {
            int t = __shfl_up_sync(0xffu, y, off);
            if (lane >= off) y += t;
        }
        ws[lane] = y;
    }
    __syncthreads();
    return x + (warp ? ws[warp - 1] : 0);
}

__global__ void k_part() {    // per-block sums of g_deg
    __shared__ int ws[8];
    int i = blockIdx.x * 256 + threadIdx.x;
    int v = (i < N_NODES) ? g_deg[i] : 0;
    int inc = block_scan_inc(v, ws);
    if (threadIdx.x == 255) g_part[blockIdx.x] = inc;
}

__global__ void k_scanpart() {  // exclusive scan of NPART partials (1 block)
    __shared__ int ws[8];
    int v = (threadIdx.x < NPART) ? g_part[threadIdx.x] : 0;
    int inc = block_scan_inc(v, ws);
    if (threadIdx.x < NPART) g_part[threadIdx.x] = inc - v;  // exclusive
}

__global__ void k_apply() {   // final row_ptr
    __shared__ int ws[8];
    int i = blockIdx.x * 256 + threadIdx.x;
    int v = (i < N_NODES) ? g_deg[i] : 0;
    int inc = block_scan_inc(v, ws);
    if (i < N_NODES) g_row_ptr[i + 1] = inc + g_part[blockIdx.x];
    if (i == 0) g_row_ptr[0] = 0;
}

__global__ void k_scatter(const int* __restrict__ src, const int* __restrict__ dst) {
    int e = blockIdx.x * blockDim.x + threadIdx.x;
    if (e < N_EDGES) {
        int d = dst[e];
        int pos = g_row_ptr[d] + atomicAdd(&g_cursor[d], 1);
        g_csr_src[pos] = src[e];
    }
}

// ---------------- gather (warp per node, unroll-4 for MLP) ------------------
__device__ __forceinline__ float2 gather_node(const float* __restrict__ h,
                                              int node, int lane) {
    float ax = 0.f, ay = 0.f;
    int e   = g_row_ptr[node];
    int end = g_row_ptr[node + 1];
    for (; e + 4 <= end; e += 4) {
        int s0 = __ldg(&g_csr_src[e]);
        int s1 = __ldg(&g_csr_src[e + 1]);
        int s2 = __ldg(&g_csr_src[e + 2]);
        int s3 = __ldg(&g_csr_src[e + 3]);
        float2 v0 = *(const float2*)(h + (size_t)s0 * F + lane * 2);
        float2 v1 = *(const float2*)(h + (size_t)s1 * F + lane * 2);
        float2 v2 = *(const float2*)(h + (size_t)s2 * F + lane * 2);
        float2 v3 = *(const float2*)(h + (size_t)s3 * F + lane * 2);
        ax += v0.x + v1.x + v2.x + v3.x;
        ay += v0.y + v1.y + v2.y + v3.y;
    }
    for (; e < end; e++) {
        int s = __ldg(&g_csr_src[e]);
        float2 v = *(const float2*)(h + (size_t)s * F + lane * 2);
        ax += v.x; ay += v.y;
    }
    return make_float2(ax, ay);
}

// ---------------- fused layer: gather + GEMM + epilogue ----------------------
// block = 128 nodes x 64 outputs, 128 threads, 8x8 micro-tile via fma.rn.f32x2
__device__ __forceinline__ void mma_phase(const float* __restrict__ tile,
                                          const float* __restrict__ Wt,
                                          unsigned long long acc[4][8],
                                          int tr, int tc) {
#pragma unroll 4
    for (int k = 0; k < 64; k++) {
        const float* ar = tile + k * TILE_PAD + tr * 8;
        ulonglong2 A0 = *(const ulonglong2*)ar;        // node pairs 0,1
        ulonglong2 A1 = *(const ulonglong2*)(ar + 4);  // node pairs 2,3
        const float* wr = Wt + k * 64 + tc * 8;
        float4 w0 = *(const float4*)wr;
        float4 w1 = *(const float4*)(wr + 4);
        unsigned long long a[4] = {A0.x, A0.y, A1.x, A1.y};
        unsigned long long wd[8];
        PACK_DUP(wd[0], w0.x); PACK_DUP(wd[1], w0.y);
        PACK_DUP(wd[2], w0.z); PACK_DUP(wd[3], w0.w);
        PACK_DUP(wd[4], w1.x); PACK_DUP(wd[5], w1.y);
        PACK_DUP(wd[6], w1.z); PACK_DUP(wd[7], w1.w);
#pragma unroll
        for (int p = 0; p < 4; p++)
#pragma unroll
            for (int j = 0; j < 8; j++)
                FMA2(acc[p][j], a[p], wd[j]);
    }
}

__global__ void __launch_bounds__(128, 4)
k_layer_fused(const float* __restrict__ h,
              const float* __restrict__ W,   // [64][129]
              const float* __restrict__ b,   // [64]
              float* __restrict__ out, int act) {
    extern __shared__ float smem[];
    float* tile = smem;                    // [64][TILE_PAD]
    float* Wt   = smem + 64 * TILE_PAD;    // [64][64]
    int tid  = threadIdx.x;
    int warp = tid >> 5, lane = tid & 31;
    int tr = tid >> 3, tc = tid & 7;       // 16 node-groups x 8 col-groups
    int base = blockIdx.x * 128;

    // Phase G: gather aggregation for this block's 128 nodes into tile[k][n]
    for (int nn = warp; nn < 128; nn += 4) {
        int node = base + nn;
        float2 a = (node < N_NODES) ? gather_node(h, node, lane)
                                    : make_float2(0.f, 0.f);
        tile[(2 * lane)     * TILE_PAD + nn] = a.x;
        tile[(2 * lane + 1) * TILE_PAD + nn] = a.y;
    }
    // stage Wt for aggr half: Wt[k][j] = W[j][64+k]
    for (int i = tid; i < 4096; i += 128) {
        int j = i >> 6, k = i & 63;
        Wt[k * 64 + j] = W[j * KW + 64 + k];
    }
    __syncthreads();

    unsigned long long acc[4][8];
#pragma unroll
    for (int p = 0; p < 4; p++)
#pragma unroll
        for (int j = 0; j < 8; j++) acc[p][j] = 0ull;

    mma_phase(tile, Wt, acc, tr, tc);
    __syncthreads();

    // restage: self half
    for (int i = tid; i < 8192; i += 128) {
        int nn = i >> 6, k = i & 63;
        int node = base + nn;
        tile[k * TILE_PAD + nn] = (node < N_NODES) ? h[(size_t)node * F + k] : 0.f;
    }
    for (int i = tid; i < 4096; i += 128) {
        int j = i >> 6, k = i & 63;
        Wt[k * 64 + j] = W[j * KW + k];
    }
    __syncthreads();

    mma_phase(tile, Wt, acc, tr, tc);

    // epilogue: rank-1 edge term + bias + activation
    float wc[8], bj[8];
#pragma unroll
    for (int j = 0; j < 8; j++) {
        int c = tc * 8 + j;
        wc[j] = W[c * KW + 128];
        bj[j] = b[c];
    }
#pragma unroll
    for (int p = 0; p < 4; p++) {
#pragma unroll
        for (int half = 0; half < 2; half++) {
            int node = base + tr * 8 + 2 * p + half;
            if (node >= N_NODES) continue;
            float hev = g_he[node];
            float o[8];
#pragma unroll
            for (int j = 0; j < 8; j++) {
                unsigned int lo = (unsigned int)(acc[p][j] & 0xffffffffull);
                unsigned int hi = (unsigned int)(acc[p][j] >> 32);
                float v = __uint_as_float(half ? hi : lo);
                v += hev * wc[j] + bj[j];
                if (act == 1)      v = fmaxf(v, 0.f);
                else if (act == 2) v = 1.f / (1.f + expf(-v));
                o[j] = v;
            }
            float* op = out + (size_t)node * F + tc * 8;
            *(float4*)op       = make_float4(o[0], o[1], o[2], o[3]);
            *(float4*)(op + 4) = make_float4(o[4], o[5], o[6], o[7]);
        }
    }
}

// ---------------- final layer: fused gather + 2-logit dot (warp per node) ---
__global__ void k_final_fused(const float* __restrict__ h,
                              const float* __restrict__ W2,  // [2][129]
                              const float* __restrict__ b2,  // [2]
                              float* __restrict__ out) {
    int wid  = (blockIdx.x * blockDim.x + threadIdx.x) >> 5;
    int lane = threadIdx.x & 31;
    if (wid >= N_NODES) return;
    float2 hv = *(const float2*)(h + (size_t)wid * F + lane * 2);
    float2 av = gather_node(h, wid, lane);
    float he = g_he[wid];
#pragma unroll
    for (int c = 0; c < 2; c++) {
        const float* w = W2 + c * KW;
        float p = hv.x * w[2 * lane] + hv.y * w[2 * lane + 1]
                + av.x * w[64 + 2 * lane] + av.y * w[64 + 2 * lane + 1];
#pragma unroll
        for (int off = 16; off; off >>= 1) p += __shfl_xor_sync(0xffffffffu, p, off);
        if (lane == 0) out[wid * 2 + c] = p + he * w[128] + b2[c];
    }
}

// ---------------- launch -----------------------------------------------------
extern "C" void kernel_launch(void* const* d_in, const int* in_sizes, int n_in,
                              void* d_out, int out_size) {
    const float* node_feat = (const float*)d_in[0];
    const float* edge_feat = (const float*)d_in[1];
    const int*   src       = (const int*)  d_in[2];
    const int*   dst       = (const int*)  d_in[3];
    const float* W1        = (const float*)d_in[4];
    const float* b1        = (const float*)d_in[5];
    const float* Wmid      = (const float*)d_in[6];
    const float* bmid      = (const float*)d_in[7];
    const float* W2        = (const float*)d_in[8];
    const float* b2        = (const float*)d_in[9];
    float* out = (float*)d_out;

    void *p0, *p1;
    cudaGetSymbolAddress(&p0, g_h0);
    cudaGetSymbolAddress(&p1, g_h1);
    float* h0 = (float*)p0;
    float* h1 = (float*)p1;

    cudaFuncSetAttribute(k_layer_fused,
                         cudaFuncAttributeMaxDynamicSharedMemorySize, SMEM_BYTES);

    // preprocessing: CSR build + constant edge aggregation (parallel scan)
    k_zero<<<(N_NODES + 255) / 256, 256>>>();
    k_hist<<<(N_EDGES + 255) / 256, 256>>>(dst, edge_feat);
    k_part<<<NPART, 256>>>();
    k_scanpart<<<1, 256>>>();
    k_apply<<<NPART, 256>>>();
    k_scatter<<<(N_EDGES + 255) / 256, 256>>>(src, dst);

    const int layer_blocks = (N_NODES + 127) / 128;

    // layer 1: node_feat -> h0 (relu)
    k_layer_fused<<<layer_blocks, 128, SMEM_BYTES>>>(node_feat, W1, b1, h0, 1);

    // 5 mid layers (relu x4, sigmoid last), ping-pong h0/h1
    const float* cur = h0;
    float* nxt = h1;
    for (int i = 0; i < 5; i++) {
        k_layer_fused<<<layer_blocks, 128, SMEM_BYTES>>>(
            cur, Wmid + (size_t)i * F * KW, bmid + (size_t)i * F, nxt, (i < 4) ? 1 : 2);
        float* t = (float*)cur; cur = nxt; nxt = t;
    }

    // final layer: 2 logits per node -> d_out
    k_final_fused<<<(N_NODES * 32 + 255) / 256, 256>>>(cur, W2, b2, out);
}

// round 8
// speedup vs baseline: 1.4533x; 1.2625x over previous
#include <cuda_runtime.h>
#include <math.h>

#define N_NODES 50000
#define N_EDGES 800000
#define F 64
#define KW 129           // 2*F + 1
#define NPART ((N_NODES + 255) / 256)   // 196
#define TILE_PAD 132     // 128 nodes + 4 pad
#define SMEM_BYTES ((64 * TILE_PAD + 64 * 64) * 4)   // 50176

// ---------------- scratch (static device globals) ---------------------------
__device__ int   g_deg[N_NODES];
__device__ int   g_cursor[N_NODES];
__device__ int   g_row_ptr[N_NODES + 1];
__device__ int   g_csr_src[N_EDGES];
__device__ int   g_part[NPART];
__device__ float g_he[N_NODES];
__device__ float g_h0[(size_t)N_NODES * F];
__device__ float g_h1[(size_t)N_NODES * F];
__device__ float g_aggr[(size_t)N_NODES * F];

// ---------------- f32x2 helpers ---------------------------------------------
#define FMA2(d, a, b) \
    asm("fma.rn.f32x2 %0, %1, %2, %0;" : "+l"(d) : "l"(a), "l"(b))
#define PACK_DUP(out, f) \
    asm("mov.b64 %0, {%1, %1};" : "=l"(out) : "f"(f))

// ---------------- preprocessing (5 launches total) ---------------------------
__global__ void k_zero() {
    int i = blockIdx.x * blockDim.x + threadIdx.x;
    if (i < N_NODES) { g_deg[i] = 0; g_cursor[i] = 0; g_he[i] = 0.f; }
}

__global__ void k_hist(const int* __restrict__ dst, const float* __restrict__ ef) {
    int e = blockIdx.x * blockDim.x + threadIdx.x;
    if (e < N_EDGES) {
        int d = dst[e];
        atomicAdd(&g_deg[d], 1);
        atomicAdd(&g_he[d], ef[e]);
    }
}

// block-level inclusive scan of one int per thread (256 threads)
__device__ __forceinline__ int block_scan_inc(int v, int* ws) {
    int lane = threadIdx.x & 31, warp = threadIdx.x >> 5;
    int x = v;
#pragma unroll
    for (int off = 1; off < 32; off <<= 1) {
        int t = __shfl_up_sync(0xffffffffu, x, off);
        if (lane >= off) x += t;
    }
    if (lane == 31) ws[warp] = x;
    __syncthreads();
    if (warp == 0 && lane < 8) {
        int y = ws[lane];
#pragma unroll
        for (int off = 1; off < 8; off <<= 1) {
            int t = __shfl_up_sync(0xffu, y, off);
            if (lane >= off) y += t;
        }
        ws[lane] = y;
    }
    __syncthreads();
    return x + (warp ? ws[warp - 1] : 0);
}

__global__ void k_part() {    // per-block sums of g_deg
    __shared__ int red[8];
    int lane = threadIdx.x & 31, warp = threadIdx.x >> 5;
    int i = blockIdx.x * 256 + threadIdx.x;
    int v = (i < N_NODES) ? g_deg[i] : 0;
#pragma unroll
    for (int off = 16; off; off >>= 1) v += __shfl_xor_sync(0xffffffffu, v, off);
    if (lane == 0) red[warp] = v;
    __syncthreads();
    if (threadIdx.x == 0) {
        int s = 0;
#pragma unroll
        for (int w = 0; w < 8; w++) s += red[w];
        g_part[blockIdx.x] = s;
    }
}

__global__ void k_apply() {   // row_ptr = prefix(partials) + local scan
    __shared__ int ws[8];
    __shared__ int sbase;
    int tid = threadIdx.x, bid = blockIdx.x;
    int lane = tid & 31, warp = tid >> 5;
    // base = sum of g_part[0..bid)
    int partial = 0;
    for (int j = tid; j < bid; j += 256) partial += g_part[j];
#pragma unroll
    for (int off = 16; off; off >>= 1)
        partial += __shfl_xor_sync(0xffffffffu, partial, off);
    if (lane == 0) ws[warp] = partial;
    __syncthreads();
    if (tid == 0) {
        int s = 0;
#pragma unroll
        for (int w = 0; w < 8; w++) s += ws[w];
        sbase = s;
    }
    __syncthreads();
    int i = bid * 256 + tid;
    int v = (i < N_NODES) ? g_deg[i] : 0;
    int inc = block_scan_inc(v, ws);
    if (i < N_NODES) g_row_ptr[i + 1] = sbase + inc;
    if (i == 0) g_row_ptr[0] = 0;
}

__global__ void k_scatter(const int* __restrict__ src, const int* __restrict__ dst) {
    int e = blockIdx.x * blockDim.x + threadIdx.x;
    if (e < N_EDGES) {
        int d = dst[e];
        int pos = g_row_ptr[d] + atomicAdd(&g_cursor[d], 1);
        g_csr_src[pos] = src[e];
    }
}

// ---------------- gather core (warp per node, unroll-4 for MLP) --------------
__device__ __forceinline__ float2 gather_node(const float* __restrict__ h,
                                              int node, int lane) {
    float ax = 0.f, ay = 0.f;
    int e   = g_row_ptr[node];
    int end = g_row_ptr[node + 1];
    for (; e + 4 <= end; e += 4) {
        int s0 = __ldg(&g_csr_src[e]);
        int s1 = __ldg(&g_csr_src[e + 1]);
        int s2 = __ldg(&g_csr_src[e + 2]);
        int s3 = __ldg(&g_csr_src[e + 3]);
        float2 v0 = *(const float2*)(h + (size_t)s0 * F + lane * 2);
        float2 v1 = *(const float2*)(h + (size_t)s1 * F + lane * 2);
        float2 v2 = *(const float2*)(h + (size_t)s2 * F + lane * 2);
        float2 v3 = *(const float2*)(h + (size_t)s3 * F + lane * 2);
        ax += v0.x + v1.x + v2.x + v3.x;
        ay += v0.y + v1.y + v2.y + v3.y;
    }
    for (; e < end; e++) {
        int s = __ldg(&g_csr_src[e]);
        float2 v = *(const float2*)(h + (size_t)s * F + lane * 2);
        ax += v.x; ay += v.y;
    }
    return make_float2(ax, ay);
}

// ---------------- aggregation kernel (high occupancy: 64 warps/SM) ----------
__global__ void k_aggr(const float* __restrict__ h) {
    int node = (blockIdx.x * blockDim.x + threadIdx.x) >> 5;
    int lane = threadIdx.x & 31;
    if (node >= N_NODES) return;
    float2 a = gather_node(h, node, lane);
    *(float2*)(g_aggr + (size_t)node * F + lane * 2) = a;
}

// ---------------- GEMM layer: out = act([h|aggr|he] @ W^T + b) ---------------
// block = 128 nodes x 64 outputs, 128 threads, 8x8 micro-tile via fma.rn.f32x2
__device__ __forceinline__ void mma_phase(const float* __restrict__ tile,
                                          const float* __restrict__ Wt,
                                          unsigned long long acc[4][8],
                                          int tr, int tc) {
#pragma unroll 4
    for (int k = 0; k < 64; k++) {
        const float* ar = tile + k * TILE_PAD + tr * 8;
        ulonglong2 A0 = *(const ulonglong2*)ar;        // node pairs 0,1
        ulonglong2 A1 = *(const ulonglong2*)(ar + 4);  // node pairs 2,3
        const float* wr = Wt + k * 64 + tc * 8;
        float4 w0 = *(const float4*)wr;
        float4 w1 = *(const float4*)(wr + 4);
        unsigned long long a[4] = {A0.x, A0.y, A1.x, A1.y};
        unsigned long long wd[8];
        PACK_DUP(wd[0], w0.x); PACK_DUP(wd[1], w0.y);
        PACK_DUP(wd[2], w0.z); PACK_DUP(wd[3], w0.w);
        PACK_DUP(wd[4], w1.x); PACK_DUP(wd[5], w1.y);
        PACK_DUP(wd[6], w1.z); PACK_DUP(wd[7], w1.w);
#pragma unroll
        for (int p = 0; p < 4; p++)
#pragma unroll
            for (int j = 0; j < 8; j++)
                FMA2(acc[p][j], a[p], wd[j]);
    }
}

__global__ void __launch_bounds__(128, 4)
k_layer(const float* __restrict__ h,
        const float* __restrict__ W,   // [64][129]
        const float* __restrict__ b,   // [64]
        float* __restrict__ out, int act) {
    extern __shared__ float smem[];
    float* tile = smem;                    // [64][TILE_PAD]
    float* Wt   = smem + 64 * TILE_PAD;    // [64][64]
    int tid = threadIdx.x;
    int tr = tid >> 3, tc = tid & 7;       // 16 node-groups x 8 col-groups
    int base = blockIdx.x * 128;

    unsigned long long acc[4][8];
#pragma unroll
    for (int p = 0; p < 4; p++)
#pragma unroll
        for (int j = 0; j < 8; j++) acc[p][j] = 0ull;

#pragma unroll
    for (int phase = 0; phase < 2; phase++) {
        const float* hp = phase ? h : g_aggr;   // phase0: aggr half (W cols 64..)
        int wofs = phase ? 0 : 64;
        __syncthreads();
        // stage tile transposed: tile[k][nn], float4 gmem loads (coalesced)
        for (int i = tid; i < 2048; i += 128) {
            int nn = i >> 4;                 // 16 float4 per node row
            int k4 = (i & 15) * 4;
            float4 v = (base + nn < N_NODES)
                     ? *(const float4*)(hp + (size_t)(base + nn) * F + k4)
                     : make_float4(0.f, 0.f, 0.f, 0.f);
            tile[(k4 + 0) * TILE_PAD + nn] = v.x;
            tile[(k4 + 1) * TILE_PAD + nn] = v.y;
            tile[(k4 + 2) * TILE_PAD + nn] = v.z;
            tile[(k4 + 3) * TILE_PAD + nn] = v.w;
        }
        // stage weight half (transposed)
        for (int i = tid; i < 4096; i += 128) {
            int j = i >> 6, k = i & 63;
            Wt[k * 64 + j] = W[j * KW + wofs + k];
        }
        __syncthreads();
        mma_phase(tile, Wt, acc, tr, tc);
    }

    // epilogue: rank-1 edge term + bias + activation
    float wc[8], bj[8];
#pragma unroll
    for (int j = 0; j < 8; j++) {
        int c = tc * 8 + j;
        wc[j] = W[c * KW + 128];
        bj[j] = b[c];
    }
#pragma unroll
    for (int p = 0; p < 4; p++) {
#pragma unroll
        for (int half = 0; half < 2; half++) {
            int node = base + tr * 8 + 2 * p + half;
            if (node >= N_NODES) continue;
            float hev = g_he[node];
            float o[8];
#pragma unroll
            for (int j = 0; j < 8; j++) {
                unsigned int lo = (unsigned int)(acc[p][j] & 0xffffffffull);
                unsigned int hi = (unsigned int)(acc[p][j] >> 32);
                float v = __uint_as_float(half ? hi : lo);
                v += hev * wc[j] + bj[j];
                if (act == 1)      v = fmaxf(v, 0.f);
                else if (act == 2) v = 1.f / (1.f + expf(-v));
                o[j] = v;
            }
            float* op = out + (size_t)node * F + tc * 8;
            *(float4*)op       = make_float4(o[0], o[1], o[2], o[3]);
            *(float4*)(op + 4) = make_float4(o[4], o[5], o[6], o[7]);
        }
    }
}

// ---------------- final layer: 2 logits per node (warp per node) -------------
__global__ void k_final(const float* __restrict__ h,
                        const float* __restrict__ W2,  // [2][129]
                        const float* __restrict__ b2,  // [2]
                        float* __restrict__ out) {
    int node = (blockIdx.x * blockDim.x + threadIdx.x) >> 5;
    int lane = threadIdx.x & 31;
    if (node >= N_NODES) return;
    float2 hv = *(const float2*)(h      + (size_t)node * F + lane * 2);
    float2 av = *(const float2*)(g_aggr + (size_t)node * F + lane * 2);
    float he = g_he[node];
#pragma unroll
    for (int c = 0; c < 2; c++) {
        const float* w = W2 + c * KW;
        float p = hv.x * w[2 * lane] + hv.y * w[2 * lane + 1]
                + av.x * w[64 + 2 * lane] + av.y * w[64 + 2 * lane + 1];
#pragma unroll
        for (int off = 16; off; off >>= 1) p += __shfl_xor_sync(0xffffffffu, p, off);
        if (lane == 0) out[node * 2 + c] = p + he * w[128] + b2[c];
    }
}

// ---------------- launch -----------------------------------------------------
extern "C" void kernel_launch(void* const* d_in, const int* in_sizes, int n_in,
                              void* d_out, int out_size) {
    const float* node_feat = (const float*)d_in[0];
    const float* edge_feat = (const float*)d_in[1];
    const int*   src       = (const int*)  d_in[2];
    const int*   dst       = (const int*)  d_in[3];
    const float* W1        = (const float*)d_in[4];
    const float* b1        = (const float*)d_in[5];
    const float* Wmid      = (const float*)d_in[6];
    const float* bmid      = (const float*)d_in[7];
    const float* W2        = (const float*)d_in[8];
    const float* b2        = (const float*)d_in[9];
    float* out = (float*)d_out;

    void *p0, *p1;
    cudaGetSymbolAddress(&p0, g_h0);
    cudaGetSymbolAddress(&p1, g_h1);
    float* h0 = (float*)p0;
    float* h1 = (float*)p1;

    cudaFuncSetAttribute(k_layer,
                         cudaFuncAttributeMaxDynamicSharedMemorySize, SMEM_BYTES);

    // preprocessing: exactly 5 launches (so ncu -s 5 profiles k_aggr)
    k_zero<<<(N_NODES + 255) / 256, 256>>>();
    k_hist<<<(N_EDGES + 255) / 256, 256>>>(dst, edge_feat);
    k_part<<<NPART, 256>>>();
    k_apply<<<NPART, 256>>>();
    k_scatter<<<(N_EDGES + 255) / 256, 256>>>(src, dst);

    const int aggr_blocks  = (N_NODES * 32 + 255) / 256;   // warp per node
    const int layer_blocks = (N_NODES + 127) / 128;

    // layer 1: node_feat -> h0 (relu)
    k_aggr<<<aggr_blocks, 256>>>(node_feat);
    k_layer<<<layer_blocks, 128, SMEM_BYTES>>>(node_feat, W1, b1, h0, 1);

    // 5 mid layers (relu x4, sigmoid last), ping-pong h0/h1
    const float* cur = h0;
    float* nxt = h1;
    for (int i = 0; i < 5; i++) {
        k_aggr<<<aggr_blocks, 256>>>(cur);
        k_layer<<<layer_blocks, 128, SMEM_BYTES>>>(
            cur, Wmid + (size_t)i * F * KW, bmid + (size_t)i * F, nxt, (i < 4) ? 1 : 2);
        float* t = (float*)cur; cur = nxt; nxt = t;
    }

    // final layer: 2 logits per node -> d_out
    k_aggr<<<aggr_blocks, 256>>>(cur);
    k_final<<<aggr_blocks, 256>>>(cur, W2, b2, out);
}